// round 2
// baseline (speedup 1.0000x reference)
#include <cuda_runtime.h>

#define MAXD 365
#define NBLK 1184
#define NTHR 256

__device__ float    g_S[MAXD];      // sum exp(clip(y)) per duration bucket
__device__ unsigned g_M[MAXD];      // event count per bucket
__device__ unsigned g_C[MAXD];      // total count per bucket (for e.sum()==0 corner)
__device__ float    g_sum_ey;       // sum of e_i * y_i
__device__ float    g_sum_y;        // sum of y_i

__global__ void cox_zero_kernel() {
    int t = threadIdx.x;
    for (int i = t; i < MAXD; i += blockDim.x) {
        g_S[i] = 0.f; g_M[i] = 0u; g_C[i] = 0u;
    }
    if (t == 0) { g_sum_ey = 0.f; g_sum_y = 0.f; }
}

__device__ __forceinline__ void cox_accum_one(
    float yy, int dd, int ec,
    float* sS, unsigned* sM, unsigned* sC,
    float& ey, float& sy)
{
    float x  = fminf(fmaxf(yy, -20.f), 20.f);
    float ex = expf(x);
    dd = dd < 0 ? 0 : (dd >= MAXD ? MAXD - 1 : dd);
    atomicAdd(&sS[dd], ex);
    atomicAdd(&sC[dd], 1u);
    if (ec) {
        atomicAdd(&sM[dd], 1u);
        ey += yy;
    }
    sy += yy;
}

__global__ void __launch_bounds__(NTHR)
cox_accum_kernel(const float* __restrict__ pred,
                 const int*   __restrict__ dur,
                 const int*   __restrict__ ev,
                 int n)
{
    __shared__ float    sS[MAXD];
    __shared__ unsigned sM[MAXD];
    __shared__ unsigned sC[MAXD];
    __shared__ float    wEy[NTHR / 32];
    __shared__ float    wSy[NTHR / 32];

    int t = threadIdx.x;
    for (int i = t; i < MAXD; i += NTHR) { sS[i] = 0.f; sM[i] = 0u; sC[i] = 0u; }
    __syncthreads();

    float ey = 0.f, sy = 0.f;

    int nv = n >> 2;  // number of vec4 packs
    const float4* p4 = (const float4*)pred;
    const int4*   d4 = (const int4*)dur;
    const int4*   e4 = (const int4*)ev;

    for (int i = blockIdx.x * NTHR + t; i < nv; i += gridDim.x * NTHR) {
        float4 y = p4[i];
        int4   d = d4[i];
        int4   e = e4[i];
        cox_accum_one(y.x, d.x, e.x, sS, sM, sC, ey, sy);
        cox_accum_one(y.y, d.y, e.y, sS, sM, sC, ey, sy);
        cox_accum_one(y.z, d.z, e.z, sS, sM, sC, ey, sy);
        cox_accum_one(y.w, d.w, e.w, sS, sM, sC, ey, sy);
    }
    // scalar tail (N divisible by 4 in practice, but stay general)
    for (int i = (nv << 2) + blockIdx.x * NTHR + t; i < n; i += gridDim.x * NTHR) {
        cox_accum_one(pred[i], dur[i], ev[i], sS, sM, sC, ey, sy);
    }

    // block reduce of ey, sy
    int lane = t & 31, wid = t >> 5;
    #pragma unroll
    for (int o = 16; o; o >>= 1) {
        ey += __shfl_down_sync(0xffffffffu, ey, o);
        sy += __shfl_down_sync(0xffffffffu, sy, o);
    }
    if (lane == 0) { wEy[wid] = ey; wSy[wid] = sy; }
    __syncthreads();
    if (t == 0) {
        float a = 0.f, b = 0.f;
        #pragma unroll
        for (int w = 0; w < NTHR / 32; w++) { a += wEy[w]; b += wSy[w]; }
        atomicAdd(&g_sum_ey, a);
        atomicAdd(&g_sum_y,  b);
    }

    // flush histograms (only non-empty buckets)
    for (int i = t; i < MAXD; i += NTHR) {
        float s = sS[i];
        if (s != 0.f) atomicAdd(&g_S[i], s);
        unsigned m = sM[i];
        if (m)        atomicAdd(&g_M[i], m);
        unsigned c = sC[i];
        if (c)        atomicAdd(&g_C[i], c);
    }
}

__global__ void __launch_bounds__(512)
cox_finalize_kernel(float* __restrict__ out, int n)
{
    __shared__ float    sR[512];
    __shared__ float    redM[512];
    __shared__ float    redC[512];
    __shared__ unsigned redN[512];

    int t = threadIdx.x;
    float    s = (t < MAXD) ? g_S[t] : 0.f;
    unsigned m = (t < MAXD) ? g_M[t] : 0u;
    unsigned c = (t < MAXD) ? g_C[t] : 0u;
    sR[t] = s;
    __syncthreads();

    // suffix (inclusive) scan: sR[t] = sum_{j>=t} S[j]
    #pragma unroll
    for (int off = 1; off < 512; off <<= 1) {
        float v = (t + off < 512) ? sR[t + off] : 0.f;
        __syncthreads();
        sR[t] += v;
        __syncthreads();
    }

    float R  = fmaxf(sR[t], 1e-12f);
    float lg = (m | c) ? logf(R) : 0.f;
    redM[t] = (float)m * lg;
    redC[t] = (float)c * lg;
    redN[t] = m;
    __syncthreads();

    #pragma unroll
    for (int off = 256; off; off >>= 1) {
        if (t < off) {
            redM[t] += redM[t + off];
            redC[t] += redC[t + off];
            redN[t] += redN[t + off];
        }
        __syncthreads();
    }

    if (t == 0) {
        unsigned nev      = redN[0];
        float sum_m_logR  = redM[0];
        float sum_c_logR  = redC[0];
        float sum_ey      = g_sum_ey;
        float sum_y       = g_sum_y;

        float total_ll, n_events;
        if (nev > 0u) {
            total_ll = sum_ey - sum_m_logR;
            n_events = fmaxf((float)nev, 1.f);
        } else {
            // reference: e -> e + 1e-8 everywhere when no events
            total_ll = 1e-8f * (sum_y - sum_c_logR);
            n_events = fmaxf(1e-8f * (float)n, 1.f);
        }
        out[0] = -total_ll / n_events;
    }
}

extern "C" void kernel_launch(void* const* d_in, const int* in_sizes, int n_in,
                              void* d_out, int out_size)
{
    const float* pred = (const float*)d_in[0];
    const int*   dur  = (const int*)d_in[1];
    const int*   ev   = (const int*)d_in[2];
    int n = in_sizes[0];

    cox_zero_kernel<<<1, 512>>>();
    cox_accum_kernel<<<NBLK, NTHR>>>(pred, dur, ev, n);
    cox_finalize_kernel<<<1, 512>>>((float*)d_out, n);
}

// round 3
// speedup vs baseline: 1.0767x; 1.0767x over previous
#include <cuda_runtime.h>

#define MAXD 365
#define NTHR 512
#define NBLK 592   // 4 blocks/SM * 148 SMs

__device__ float    g_S[MAXD];      // sum exp(clip(y)) per duration bucket
__device__ unsigned g_M[MAXD];      // event count per bucket
__device__ unsigned g_C[MAXD];      // total count per bucket (no-events corner)
__device__ float    g_sum_ey;       // sum e_i * y_i
__device__ float    g_sum_y;        // sum y_i
__device__ unsigned g_done;         // completion counter

__global__ void __launch_bounds__(NTHR)
cox_fused_kernel(const float* __restrict__ pred,
                 const int*   __restrict__ dur,
                 const int*   __restrict__ ev,
                 float* __restrict__ out,
                 int n)
{
    __shared__ float    sS[MAXD];
    __shared__ unsigned sMC[MAXD];          // low16 = count, high16 = event count
    __shared__ float    wEy[NTHR / 32];
    __shared__ float    wSy[NTHR / 32];
    __shared__ unsigned sIsLast;

    int t = threadIdx.x;
    for (int i = t; i < MAXD; i += NTHR) { sS[i] = 0.f; sMC[i] = 0u; }
    __syncthreads();

    float ey = 0.f, sy = 0.f;

    int nv = n >> 2;
    const float4* p4 = (const float4*)pred;
    const int4*   d4 = (const int4*)dur;
    const int4*   e4 = (const int4*)ev;

    for (int i = blockIdx.x * NTHR + t; i < nv; i += gridDim.x * NTHR) {
        float4 y = p4[i];
        int4   d = d4[i];
        int4   e = e4[i];
        #pragma unroll
        for (int k = 0; k < 4; k++) {
            float yy = (&y.x)[k];
            int   dd = (&d.x)[k];
            int   ec = (&e.x)[k];
            float x  = fminf(fmaxf(yy, -20.f), 20.f);
            float ex = __expf(x);
            dd = dd < 0 ? 0 : (dd >= MAXD ? MAXD - 1 : dd);
            atomicAdd(&sS[dd], ex);
            atomicAdd(&sMC[dd], 1u | ((unsigned)ec << 16));
            ey += (float)ec * yy;
            sy += yy;
        }
    }
    // scalar tail
    for (int i = (nv << 2) + blockIdx.x * NTHR + t; i < n; i += gridDim.x * NTHR) {
        float yy = pred[i];
        int   dd = dur[i];
        int   ec = ev[i];
        float x  = fminf(fmaxf(yy, -20.f), 20.f);
        float ex = __expf(x);
        dd = dd < 0 ? 0 : (dd >= MAXD ? MAXD - 1 : dd);
        atomicAdd(&sS[dd], ex);
        atomicAdd(&sMC[dd], 1u | ((unsigned)ec << 16));
        ey += (float)ec * yy;
        sy += yy;
    }

    // block reduce ey, sy
    int lane = t & 31, wid = t >> 5;
    #pragma unroll
    for (int o = 16; o; o >>= 1) {
        ey += __shfl_down_sync(0xffffffffu, ey, o);
        sy += __shfl_down_sync(0xffffffffu, sy, o);
    }
    if (lane == 0) { wEy[wid] = ey; wSy[wid] = sy; }
    __syncthreads();
    if (t == 0) {
        float a = 0.f, b = 0.f;
        #pragma unroll
        for (int w = 0; w < NTHR / 32; w++) { a += wEy[w]; b += wSy[w]; }
        atomicAdd(&g_sum_ey, a);
        atomicAdd(&g_sum_y,  b);
    }

    // flush histograms to globals (skip empty buckets)
    for (int i = t; i < MAXD; i += NTHR) {
        float s = sS[i];
        if (s != 0.f) atomicAdd(&g_S[i], s);
        unsigned mc = sMC[i];
        if (mc) {
            unsigned c = mc & 0xFFFFu;
            unsigned m = mc >> 16;
            atomicAdd(&g_C[i], c);
            if (m) atomicAdd(&g_M[i], m);
        }
    }

    // ---- last-block-done: finalize in this kernel ----
    __threadfence();
    if (t == 0) {
        unsigned ticket = atomicAdd(&g_done, 1u);
        sIsLast = (ticket == gridDim.x - 1u) ? 1u : 0u;
    }
    __syncthreads();
    if (!sIsLast) return;

    // last block: suffix scan of 365 buckets + reduction
    __shared__ float    sR[NTHR];
    __shared__ float    redM[NTHR];
    __shared__ float    redC[NTHR];
    __shared__ unsigned redN[NTHR];

    float    s = (t < MAXD) ? __ldcg(&g_S[t]) : 0.f;
    unsigned m = (t < MAXD) ? __ldcg(&g_M[t]) : 0u;
    unsigned c = (t < MAXD) ? __ldcg(&g_C[t]) : 0u;
    sR[t] = s;
    __syncthreads();

    // Hillis-Steele inclusive suffix scan
    #pragma unroll
    for (int off = 1; off < NTHR; off <<= 1) {
        float v = (t + off < NTHR) ? sR[t + off] : 0.f;
        __syncthreads();
        sR[t] += v;
        __syncthreads();
    }

    float R  = fmaxf(sR[t], 1e-12f);
    float lg = (m | c) ? logf(R) : 0.f;
    redM[t] = (float)m * lg;
    redC[t] = (float)c * lg;
    redN[t] = m;
    __syncthreads();

    #pragma unroll
    for (int off = NTHR / 2; off; off >>= 1) {
        if (t < off) {
            redM[t] += redM[t + off];
            redC[t] += redC[t + off];
            redN[t] += redN[t + off];
        }
        __syncthreads();
    }

    if (t == 0) {
        unsigned nev     = redN[0];
        float sum_m_logR = redM[0];
        float sum_c_logR = redC[0];
        float sum_ey     = __ldcg(&g_sum_ey);
        float sum_y      = __ldcg(&g_sum_y);

        float total_ll, n_events;
        if (nev > 0u) {
            total_ll = sum_ey - sum_m_logR;
            n_events = fmaxf((float)nev, 1.f);
        } else {
            // reference: e -> e + 1e-8 everywhere when no events
            total_ll = 1e-8f * (sum_y - sum_c_logR);
            n_events = fmaxf(1e-8f * (float)n, 1.f);
        }
        out[0] = -total_ll / n_events;
    }

    // re-zero globals for the next graph replay
    for (int i = t; i < MAXD; i += NTHR) {
        g_S[i] = 0.f; g_M[i] = 0u; g_C[i] = 0u;
    }
    if (t == 0) { g_sum_ey = 0.f; g_sum_y = 0.f; g_done = 0u; }
}

extern "C" void kernel_launch(void* const* d_in, const int* in_sizes, int n_in,
                              void* d_out, int out_size)
{
    const float* pred = (const float*)d_in[0];
    const int*   dur  = (const int*)d_in[1];
    const int*   ev   = (const int*)d_in[2];
    int n = in_sizes[0];

    cox_fused_kernel<<<NBLK, NTHR>>>(pred, dur, ev, (float*)d_out, n);
}